// round 6
// baseline (speedup 1.0000x reference)
#include <cuda_runtime.h>
#include <math.h>

#define NB 8
#define CC 3
#define HH 512
#define WW 512
#define HY 256
#define WY 256
#define GG 5
#define MM 3
#define LOG2E 1.4426950408889634f

// ---------------- parameter block: computed on device, then memcpy'd to __constant__ ----------------
struct __align__(16) Prm {
    float4 P0[GG];        // mu0,mu1,mu2, LOG2E*(-0.5*logdet + log_softmax(pi))
    float4 P1[GG];        // LOG2E * {-0.5*Sinv00, -0.5*Sinv11, -0.5*Sinv22, -Sinv01}
    float4 P2[GG];        // LOG2E * {-Sinv02, -Sinv12}, 0, 0
    float4 mf[GG*MM];     // {c, aL, aR, 0} with a = sqrt(0.5*LOG2E)/sigma
    float  we[4];         // even-row upsample taps (x2 folded)
    float  wo[4];         // odd-row upsample taps  (x2 folded)
};

__constant__ Prm c_prm;
__device__   Prm g_prm;
__device__ float g_y[NB*CC*HY*WY];   // downsampled pyramid level (6.3 MB)

__device__ __forceinline__ float softplus_f(float x){
    if (x > 20.f) return x;
    return log1pf(__expf(x));
}
__device__ __forceinline__ float ex2f(float x){
    float y; asm("ex2.approx.ftz.f32 %0, %1;" : "=f"(y) : "f"(x)); return y;
}

// fp32 1D gaussian weights
__device__ __forceinline__ void gauss7(float* gw){
    float s = 0.f;
    #pragma unroll
    for (int k = 0; k < 7; k++){
        float r = (float)(k - 3);
        gw[k] = __expf(-r*r/(2.f*0.9f*0.9f));
        s += gw[k];
    }
    float is = 1.f/s;
    #pragma unroll
    for (int k = 0; k < 7; k++) gw[k] *= is;
}

// ---------------- setup work (runs inside down_kernel's extra z-slice, fp32) ----------------
__device__ void do_setup(const float* __restrict__ mu,
                         const float* __restrict__ L_raw,
                         const float* __restrict__ pi,
                         const float* __restrict__ mf_c,
                         const float* __restrict__ mf_sL,
                         const float* __restrict__ mf_sR,
                         int t)
{
    float gw[7];
    gauss7(gw);

    if (t == 0){
        // 2D transposed-conv kernel is 4*(g outer g): fold sqrt(4)=2 into EACH 1D stage.
        g_prm.we[0]=2.f*gw[1]; g_prm.we[1]=2.f*gw[3]; g_prm.we[2]=2.f*gw[5]; g_prm.we[3]=0.f;
        g_prm.wo[0]=2.f*gw[0]; g_prm.wo[1]=2.f*gw[2]; g_prm.wo[2]=2.f*gw[4]; g_prm.wo[3]=2.f*gw[6];
    }

    // per-Gaussian parameter block: parallel over g, fp32 (Sigma well-conditioned)
    if (t < GG){
        int g = t;
        float pmx = -3.4e38f;
        for (int q = 0; q < GG; q++) pmx = fmaxf(pmx, pi[q]);
        float ps = 0.f;
        for (int q = 0; q < GG; q++) ps += __expf(pi[q] - pmx);
        float lse = pmx + logf(ps);

        float L[3][3];
        for (int i = 0; i < 3; i++)
            for (int j = 0; j < 3; j++)
                L[i][j] = (j < i) ? L_raw[(g*3+i)*3+j] : 0.f;
        for (int i = 0; i < 3; i++)
            L[i][i] = softplus_f(softplus_f(L_raw[(g*3+i)*3+i]) + 1e-4f) + 1e-4f;

        float S[3][3];
        for (int i = 0; i < 3; i++)
            for (int j = 0; j < 3; j++){
                float acc = 0.f;
                for (int k = 0; k < 3; k++) acc += L[i][k]*L[j][k];
                S[i][j] = acc + (i==j ? 1e-4f : 0.f);
            }

        float detS = S[0][0]*(S[1][1]*S[2][2]-S[1][2]*S[1][2])
                   - S[0][1]*(S[0][1]*S[2][2]-S[1][2]*S[0][2])
                   + S[0][2]*(S[0][1]*S[1][2]-S[1][1]*S[0][2]);

        float A00=S[0][0]+1e-3f, A11=S[1][1]+1e-3f, A22=S[2][2]+1e-3f;
        float A01=S[0][1],       A02=S[0][2],       A12=S[1][2];
        float detA = A00*(A11*A22-A12*A12) - A01*(A01*A22-A12*A02) + A02*(A01*A12-A11*A02);
        float id = 1.f/detA;
        float i00 = (A11*A22-A12*A12)*id;
        float i11 = (A00*A22-A02*A02)*id;
        float i22 = (A00*A11-A01*A01)*id;
        float i01 = (A02*A12-A01*A22)*id;
        float i02 = (A01*A12-A02*A11)*id;
        float i12 = (A01*A02-A00*A12)*id;

        // everything that enters the logit is pre-scaled by LOG2E (exp2 domain)
        g_prm.P0[g] = make_float4(mu[g*3+0], mu[g*3+1], mu[g*3+2],
                                  LOG2E*(-0.5f*logf(detS) + (pi[g]-lse)));
        g_prm.P1[g] = make_float4(LOG2E*-0.5f*i00, LOG2E*-0.5f*i11, LOG2E*-0.5f*i22, LOG2E*-i01);
        g_prm.P2[g] = make_float4(LOG2E*-i02, LOG2E*-i12, 0.f, 0.f);
    }

    // membership params: a = sqrt(0.5*LOG2E)/sigma so that e_m = exp2(-( (r-c)*a )^2)
    if (t < GG*MM){
        float sc = sqrtf(0.5f*LOG2E);
        float sl = softplus_f(mf_sL[t]) + 1e-12f;
        float sr = softplus_f(mf_sR[t]) + 1e-12f;
        g_prm.mf[t] = make_float4(mf_c[t], sc/sl, sc/sr, 0.f);
    }
}

// ---------------- kernel 1: reflect-pad blur downsample  (+ setup in extra z-slice) ----------------
__global__ __launch_bounds__(256)
void down_kernel(const float* __restrict__ x,
                 const float* __restrict__ mu,
                 const float* __restrict__ L_raw,
                 const float* __restrict__ pi,
                 const float* __restrict__ mf_c,
                 const float* __restrict__ mf_sL,
                 const float* __restrict__ mf_sR)
{
    __shared__ float xs[37][136];   // x tile (37 rows x 133 used cols)
    __shared__ float tmp[16][136];  // vertically blurred, stride-2 rows

    int t  = threadIdx.x;
    int nc = blockIdx.z;            // n*3 + c  (or NB*CC -> setup slice)

    if (nc == NB*CC){
        if (blockIdx.x == 0 && blockIdx.y == 0)
            do_setup(mu, L_raw, pi, mf_c, mf_sL, mf_sR, t);
        return;
    }

    int j0 = blockIdx.x * 64;       // y col tile origin
    int i0 = blockIdx.y * 16;       // y row tile origin

    const float* xb = x + (size_t)nc * (HH*WW);

    float w[7];
    gauss7(w);

    int r0 = 2*i0 - 3, c0 = 2*j0 - 3;
    for (int idx = t; idx < 37*133; idx += 256){
        int ri = idx / 133, ci = idx - ri*133;
        int rr = r0 + ri; rr = (rr < 0) ? -rr : ((rr > 511) ? 1022 - rr : rr);
        int cc = c0 + ci; cc = (cc < 0) ? -cc : ((cc > 511) ? 1022 - cc : cc);
        xs[ri][ci] = __ldcs(&xb[rr*WW + cc]);
    }
    __syncthreads();

    for (int idx = t; idx < 16*133; idx += 256){
        int r = idx / 133, q = idx - r*133;
        float s = 0.f;
        #pragma unroll
        for (int a = 0; a < 7; a++) s += w[a]*xs[2*r+a][q];
        tmp[r][q] = s;
    }
    __syncthreads();

    float* yb = g_y + (size_t)nc * (HY*WY);
    int jl = t & 63;
    int rb = t >> 6;
    #pragma unroll
    for (int rr = 0; rr < 4; rr++){
        int r = rb*4 + rr;
        float s = 0.f;
        #pragma unroll
        for (int b = 0; b < 7; b++) s += w[b]*tmp[r][2*jl+b];
        yb[(i0+r)*WY + j0 + jl] = s;
    }
}

// ---------------- kernel 2: fused upsample + GMM + membership, all params in __constant__ ----------------
__global__ __launch_bounds__(256)
void up_gmm_kernel(float* __restrict__ out)
{
    __shared__ float yt[3][19][20];             // y tile (3 ch, zero-padded at image border)
    __shared__ float rs[3][19][32];             // horizontal upsample row-sums per output col
    __shared__ __align__(16) float stage[256*15]; // output staging (stride-15: conflict-free)

    int tx = threadIdx.x, ty = threadIdx.y;
    int t  = ty*32 + tx;
    int v0 = blockIdx.x * 32;
    int u0 = blockIdx.y * 32;
    int n  = blockIdx.z;

    int iy0 = u0/2 - 1, jy0 = v0/2 - 1;
    for (int idx = t; idx < 3*19*19; idx += 256){
        int c   = idx / 361;
        int rem = idx - c*361;
        int li  = rem / 19;
        int lj  = rem - li*19;
        int gi = iy0 + li, gj = jy0 + lj;
        float v = 0.f;
        if ((unsigned)gi < 256u && (unsigned)gj < 256u)
            v = g_y[((n*3 + c) << 16) + (gi << 8) + gj];
        yt[c][li][lj] = v;
    }
    __syncthreads();

    // horizontal composite-upsample row sums: rs[c][i][vl]
    for (int idx = t; idx < 3*19*32; idx += 256){
        int c   = idx / 608;
        int rem = idx - c*608;
        int li  = rem >> 5;
        int vl  = rem & 31;
        float s;
        if (vl & 1){
            int lj = (vl - 1) >> 1;
            s = c_prm.wo[0]*yt[c][li][lj]   + c_prm.wo[1]*yt[c][li][lj+1]
              + c_prm.wo[2]*yt[c][li][lj+2] + c_prm.wo[3]*yt[c][li][lj+3];
        } else {
            int lj = vl >> 1;
            s = c_prm.we[0]*yt[c][li][lj] + c_prm.we[1]*yt[c][li][lj+1] + c_prm.we[2]*yt[c][li][lj+2];
        }
        rs[c][li][vl] = s;
    }
    __syncthreads();

    for (int slab = 0; slab < 4; slab++){
        int ul = slab*8 + ty;   // local output row; parity warp-uniform (ty fixed)

        float xr0, xr1, xr2;
        if (ul & 1){
            int li0 = (ul - 1) >> 1;
            xr0 = c_prm.wo[0]*rs[0][li0][tx] + c_prm.wo[1]*rs[0][li0+1][tx] + c_prm.wo[2]*rs[0][li0+2][tx] + c_prm.wo[3]*rs[0][li0+3][tx];
            xr1 = c_prm.wo[0]*rs[1][li0][tx] + c_prm.wo[1]*rs[1][li0+1][tx] + c_prm.wo[2]*rs[1][li0+2][tx] + c_prm.wo[3]*rs[1][li0+3][tx];
            xr2 = c_prm.wo[0]*rs[2][li0][tx] + c_prm.wo[1]*rs[2][li0+1][tx] + c_prm.wo[2]*rs[2][li0+2][tx] + c_prm.wo[3]*rs[2][li0+3][tx];
        } else {
            int li0 = ul >> 1;
            xr0 = c_prm.we[0]*rs[0][li0][tx] + c_prm.we[1]*rs[0][li0+1][tx] + c_prm.we[2]*rs[0][li0+2][tx];
            xr1 = c_prm.we[0]*rs[1][li0][tx] + c_prm.we[1]*rs[1][li0+1][tx] + c_prm.we[2]*rs[1][li0+2][tx];
            xr2 = c_prm.we[0]*rs[2][li0][tx] + c_prm.we[1]*rs[2][li0+1][tx] + c_prm.we[2]*rs[2][li0+2][tx];
        }

        // GMM logits in exp2 domain + softmax over G (params from constant memory)
        float lg[GG];
        float mx = -3.4e38f;
        #pragma unroll
        for (int g = 0; g < GG; g++){
            float4 p0 = c_prm.P0[g], p1 = c_prm.P1[g], p2 = c_prm.P2[g];
            float d0 = xr0 - p0.x, d1 = xr1 - p0.y, d2 = xr2 - p0.z;
            float q = p0.w
                    + p1.x*d0*d0 + p1.y*d1*d1 + p1.z*d2*d2
                    + p1.w*d0*d1 + p2.x*d0*d2 + p2.y*d1*d2;
            lg[g] = q;
            mx = fmaxf(mx, q);
        }
        float e[GG], ssum = 0.f;
        #pragma unroll
        for (int g = 0; g < GG; g++){ e[g] = ex2f(lg[g] - mx); ssum += e[g]; }
        float inv = __fdividef(1.0f, ssum);

        // membership: direct evaluation (z in [-1,0] -> no max-subtraction needed; exp2 domain)
        float* st = &stage[t*15];
        #pragma unroll
        for (int g = 0; g < GG; g++){
            float r = e[g]*inv;                  // resp in [0,1]
            float es[MM], s2 = 0.f;
            #pragma unroll
            for (int m = 0; m < MM; m++){
                float4 p = c_prm.mf[g*MM+m];     // {c, aL, aR, 0}
                float a = (r < p.x) ? p.y : p.z;
                float d = (r - p.x)*a;
                es[m] = ex2f(-d*d);
                s2 += es[m];
            }
            float inv2 = __fdividef(1.0f, s2);
            st[g*3+0] = es[0]*inv2;
            st[g*3+1] = es[1]*inv2;
            st[g*3+2] = es[2]*inv2;
        }
        __syncthreads();

        // coalesced streaming float4 flush: 8 rows x 480 floats = 960 float4
        for (int idx = t; idx < 960; idx += 256){
            int r  = idx / 120;
            int c4 = idx - r*120;
            int u  = u0 + slab*8 + r;
            size_t base = (((size_t)(n*512 + u))*512 + v0)*15 + (size_t)c4*4;
            __stcs((float4*)&out[base], *(const float4*)&stage[r*480 + c4*4]);
        }
        __syncthreads();
    }
}

// ---------------- launch ----------------
extern "C" void kernel_launch(void* const* d_in, const int* in_sizes, int n_in,
                              void* d_out, int out_size)
{
    (void)in_sizes; (void)n_in; (void)out_size;
    const float* x     = (const float*)d_in[0];
    const float* mu    = (const float*)d_in[1];
    const float* L_raw = (const float*)d_in[2];
    const float* pi    = (const float*)d_in[3];
    const float* mf_c  = (const float*)d_in[4];
    const float* mf_sL = (const float*)d_in[5];
    const float* mf_sR = (const float*)d_in[6];
    float* out = (float*)d_out;

    down_kernel<<<dim3(WY/64, HY/16, NB*CC + 1), 256>>>(x, mu, L_raw, pi, mf_c, mf_sL, mf_sR);

    // D2D copy of the device-computed params into __constant__ (graph-capturable memcpy node)
    void* src = nullptr;
    cudaGetSymbolAddress(&src, g_prm);
    cudaMemcpyToSymbolAsync(c_prm, src, sizeof(Prm), 0, cudaMemcpyDeviceToDevice, 0);

    up_gmm_kernel<<<dim3(WW/32, HH/32, NB), dim3(32, 8)>>>(out);
}